// round 6
// baseline (speedup 1.0000x reference)
#include <cuda_runtime.h>
#include <math.h>

#define NVERT 2562
#define DEPTH 8
#define NTOK  (NVERT * DEPTH)   // 20496
#define CDIM  512
#define NHEAD 8
#define HD    64
#define KNBR  8
#define HID   2048
#define C3    1536
#define LN_EPS 1e-5f
#define KT    16                // GEMM k-tile

typedef unsigned long long u64;

// ---------------- scratch (device globals; no allocation allowed) -------------
__device__ float g_xn [(size_t)NTOK * CDIM]; // LN output (reused for LN1 & LN2)
__device__ float g_qkv[(size_t)NTOK * C3];   // qkv projections
__device__ float g_y  [(size_t)NTOK * CDIM]; // attention output
__device__ float g_x1 [(size_t)NTOK * CDIM]; // x + proj(y)  (residual 1)
__device__ float g_h  [(size_t)NTOK * HID];  // fc1/gelu activations

// ---------------- packed f32x2 helpers (sm_100+/sm_103a) ----------------------
__device__ __forceinline__ u64 pack2(float lo, float hi) {
    u64 r; asm("mov.b64 %0, {%1, %2};" : "=l"(r) : "f"(lo), "f"(hi)); return r;
}
__device__ __forceinline__ void unpack2(u64 v, float& lo, float& hi) {
    asm("mov.b64 {%0, %1}, %2;" : "=f"(lo), "=f"(hi) : "l"(v));
}
__device__ __forceinline__ u64 ffma2(u64 a, u64 b, u64 c) {
    u64 d; asm("fma.rn.f32x2 %0, %1, %2, %3;" : "=l"(d) : "l"(a), "l"(b), "l"(c));
    return d;
}

// ---------------- LayerNorm: one block (128 thr, float4) per token ------------
__global__ void ln_kernel(const float* __restrict__ x,
                          const float* __restrict__ w,
                          const float* __restrict__ b,
                          float* __restrict__ out)
{
    __shared__ float sred[4];
    __shared__ float sbc;
    const int t   = blockIdx.x;
    const int tid = threadIdx.x;          // 128 threads, 4 elems each
    const int lane = tid & 31, warp = tid >> 5;
    const float* xr = x + (size_t)t * CDIM;

    float4 v = *(const float4*)(xr + tid * 4);

    // ---- mean ----
    float s = (v.x + v.y) + (v.z + v.w);
    #pragma unroll
    for (int o = 16; o > 0; o >>= 1) s += __shfl_xor_sync(0xffffffffu, s, o);
    if (lane == 0) sred[warp] = s;
    __syncthreads();
    if (warp == 0) {
        float r = (lane < 4) ? sred[lane] : 0.f;
        #pragma unroll
        for (int o = 2; o > 0; o >>= 1) r += __shfl_xor_sync(0xffffffffu, r, o);
        if (lane == 0) sbc = r;
    }
    __syncthreads();
    const float m = sbc * (1.0f / CDIM);

    // ---- var ----
    const float d0 = v.x - m, d1 = v.y - m, d2 = v.z - m, d3 = v.w - m;
    float sq = (d0 * d0 + d1 * d1) + (d2 * d2 + d3 * d3);
    #pragma unroll
    for (int o = 16; o > 0; o >>= 1) sq += __shfl_xor_sync(0xffffffffu, sq, o);
    __syncthreads();                       // protect sred reuse
    if (lane == 0) sred[warp] = sq;
    __syncthreads();
    if (warp == 0) {
        float r = (lane < 4) ? sred[lane] : 0.f;
        #pragma unroll
        for (int o = 2; o > 0; o >>= 1) r += __shfl_xor_sync(0xffffffffu, r, o);
        if (lane == 0) sbc = r;
    }
    __syncthreads();
    const float inv = rsqrtf(sbc * (1.0f / CDIM) + LN_EPS);

    const int c0 = tid * 4;
    float4 wv = *(const float4*)(w + c0);
    float4 bv = *(const float4*)(b + c0);
    float4 o;
    o.x = d0 * inv * wv.x + bv.x;
    o.y = d1 * inv * wv.y + bv.y;
    o.z = d2 * inv * wv.z + bv.z;
    o.w = d3 * inv * wv.w + bv.w;
    *(float4*)(out + (size_t)t * CDIM + c0) = o;
}

// ---------------- SGEMM: C[M,N] = A[M,K] * B[N,K]^T + bias (+ epilogue) -------
// 128x128 tile, compile-time K, kTile=16, double-buffered smem, register
// prefetch, f32x2 FMA. Fragments split 4+4 at distance 64 -> conflict-free LDS.
// EPI: 0 = bias only, 1 = bias + exact GELU, 2 = bias + residual add
template <int EPI, int KDIM>
__global__ void __launch_bounds__(256)
sgemm_tn(const float* __restrict__ A, const float* __restrict__ B,
         const float* __restrict__ bias, const float* __restrict__ res,
         float* __restrict__ Cout, int M, int N)
{
    __shared__ float As[2][KT][128];
    __shared__ float Bs[2][KT][128];

    const int tid = threadIdx.x;
    const int tx = tid & 15;       // cols tx*4 and 64+tx*4
    const int ty = tid >> 4;       // rows ty*4 and 64+ty*4
    const int row0 = blockIdx.y * 128;
    const int col0 = blockIdx.x * 128;

    const int lr = tid >> 1;               // 0..127 (tile row loaded)
    const int lk = (tid & 1) * 8;          // 0 or 8 (k sub-offset)
    const int arow = row0 + lr;
    // clamped row: tail rows load duplicate data; epilogue guards writes.
    const float* Aptr = A + (size_t)min(arow, M - 1) * KDIM + lk;
    const float* Bptr = B + (size_t)(col0 + lr) * KDIM + lk; // N multiple of 128

    u64 acc[8][4];
    #pragma unroll
    for (int i = 0; i < 8; i++)
        #pragma unroll
        for (int j = 0; j < 4; j++) acc[i][j] = 0ULL;

    // prologue: load k-tile 0, store to buf 0, sync, prefetch k-tile 1
    float4 a4[2], b4[2];
    a4[0] = *(const float4*)(Aptr);     a4[1] = *(const float4*)(Aptr + 4);
    b4[0] = *(const float4*)(Bptr);     b4[1] = *(const float4*)(Bptr + 4);
    #pragma unroll
    for (int i = 0; i < 4; i++) {
        As[0][lk + i][lr]     = (&a4[0].x)[i];
        As[0][lk + 4 + i][lr] = (&a4[1].x)[i];
        Bs[0][lk + i][lr]     = (&b4[0].x)[i];
        Bs[0][lk + 4 + i][lr] = (&b4[1].x)[i];
    }
    __syncthreads();
    a4[0] = *(const float4*)(Aptr + KT);  a4[1] = *(const float4*)(Aptr + KT + 4);
    b4[0] = *(const float4*)(Bptr + KT);  b4[1] = *(const float4*)(Bptr + KT + 4);

    int cur = 0;
    #pragma unroll 1
    for (int k0 = 0; k0 < KDIM; k0 += KT) {
        // compute on buf cur
        #pragma unroll
        for (int k = 0; k < KT; k++) {
            float4 f0 = *(const float4*)&As[cur][k][ty * 4];
            float4 f1 = *(const float4*)&As[cur][k][ty * 4 + 64];
            float4 g0 = *(const float4*)&Bs[cur][k][tx * 4];
            float4 g1 = *(const float4*)&Bs[cur][k][tx * 4 + 64];
            u64 bb[4] = { pack2(g0.x, g0.y), pack2(g0.z, g0.w),
                          pack2(g1.x, g1.y), pack2(g1.z, g1.w) };
            float av[8] = {f0.x, f0.y, f0.z, f0.w, f1.x, f1.y, f1.z, f1.w};
            #pragma unroll
            for (int i = 0; i < 8; i++) {
                const u64 aa = pack2(av[i], av[i]);
                #pragma unroll
                for (int j = 0; j < 4; j++)
                    acc[i][j] = ffma2(aa, bb[j], acc[i][j]);
            }
        }
        if (k0 + KT < KDIM) {
            const int nxt = cur ^ 1;
            #pragma unroll
            for (int i = 0; i < 4; i++) {
                As[nxt][lk + i][lr]     = (&a4[0].x)[i];
                As[nxt][lk + 4 + i][lr] = (&a4[1].x)[i];
                Bs[nxt][lk + i][lr]     = (&b4[0].x)[i];
                Bs[nxt][lk + 4 + i][lr] = (&b4[1].x)[i];
            }
            __syncthreads();
            if (k0 + 2 * KT < KDIM) {   // prefetch the tile after next
                const int kn = k0 + 2 * KT;
                a4[0] = *(const float4*)(Aptr + kn);  a4[1] = *(const float4*)(Aptr + kn + 4);
                b4[0] = *(const float4*)(Bptr + kn);  b4[1] = *(const float4*)(Bptr + kn + 4);
            }
            cur = nxt;
        }
    }

    // epilogue: rows ty*4+i (i<4) and 64+ty*4+(i-4); cols tx*4 / 64+tx*4
    float bv[8];
    #pragma unroll
    for (int j = 0; j < 4; j++) {
        bv[j]     = __ldg(&bias[col0 + tx * 4 + j]);
        bv[4 + j] = __ldg(&bias[col0 + 64 + tx * 4 + j]);
    }

    #pragma unroll
    for (int i = 0; i < 8; i++) {
        const int r = row0 + ((i < 4) ? (ty * 4 + i) : (64 + ty * 4 + i - 4));
        if (r >= M) continue;
        float c[8];
        #pragma unroll
        for (int j = 0; j < 4; j++) unpack2(acc[i][j], c[2 * j], c[2 * j + 1]);
        #pragma unroll
        for (int half = 0; half < 2; half++) {
            float* crow = Cout + (size_t)r * N + col0 + half * 64 + tx * 4;
            const float* rrow = (EPI == 2)
                ? (res + (size_t)r * N + col0 + half * 64 + tx * 4) : nullptr;
            float4 o;
            float* op = &o.x;
            #pragma unroll
            for (int j = 0; j < 4; j++) {
                float v = c[half * 4 + j] + bv[half * 4 + j];
                if (EPI == 1) v = 0.5f * v * (1.0f + erff(v * 0.70710678118654752f));
                if (EPI == 2) v += __ldg(&rrow[j]);
                op[j] = v;
            }
            *(float4*)crow = o;
        }
    }
}

// ---------------- sparse neighbor attention -----------------------------------
// 1 block per token (n,d); 8 warps = 8 heads. hd=64 -> 2 floats/lane.
__global__ void __launch_bounds__(256)
attn_kernel(const float* __restrict__ qkv,
            const int* __restrict__ which,
            const int* __restrict__ mask,
            float* __restrict__ y)
{
    const int t = blockIdx.x;            // token = n*DEPTH + d
    const int n = t / DEPTH;
    const int d = t % DEPTH;
    const int lane = threadIdx.x & 31;
    const int h = threadIdx.x >> 5;      // head = warp

    const float* qrow = qkv + (size_t)t * C3 + h * HD;
    const float q0 = qrow[lane]      * 8.0f;   // hd^0.5 = 8
    const float q1 = qrow[lane + 32] * 8.0f;

    int   nbt[KNBR];
    float sc [KNBR];
    #pragma unroll
    for (int kk = 0; kk < KNBR; kk++) {
        const int nb = __ldg(&which[n * KNBR + kk]);
        nbt[kk] = nb * DEPTH + d;
        const float* krow = qkv + (size_t)nbt[kk] * C3 + 512 + h * HD;
        float s = q0 * krow[lane] + q1 * krow[lane + 32];
        #pragma unroll
        for (int o = 16; o > 0; o >>= 1) s += __shfl_xor_sync(0xffffffffu, s, o);
        sc[kk] = (__ldg(&mask[n * KNBR + kk]) > 0) ? s : -1e9f;
    }

    // softmax over 8 (all lanes redundantly)
    float mx = sc[0];
    #pragma unroll
    for (int kk = 1; kk < KNBR; kk++) mx = fmaxf(mx, sc[kk]);
    float sum = 0.f;
    #pragma unroll
    for (int kk = 0; kk < KNBR; kk++) { sc[kk] = __expf(sc[kk] - mx); sum += sc[kk]; }
    const float rinv = 1.0f / sum;

    float o0 = 0.f, o1 = 0.f;
    #pragma unroll
    for (int kk = 0; kk < KNBR; kk++) {
        const float p = sc[kk] * rinv;
        const float* vrow = qkv + (size_t)nbt[kk] * C3 + 1024 + h * HD;
        o0 = fmaf(p, vrow[lane],      o0);
        o1 = fmaf(p, vrow[lane + 32], o1);
    }
    float* yr = y + (size_t)t * CDIM + h * HD;
    yr[lane]      = o0;
    yr[lane + 32] = o1;
}

// ---------------- launch ------------------------------------------------------
extern "C" void kernel_launch(void* const* d_in, const int* in_sizes, int n_in,
                              void* d_out, int out_size)
{
    const float* x      = (const float*)d_in[0];
    const int*   which  = (const int*)  d_in[1];
    const int*   mask   = (const int*)  d_in[2];
    const float* ln1_w  = (const float*)d_in[3];
    const float* ln1_b  = (const float*)d_in[4];
    const float* qkv_w  = (const float*)d_in[5];
    const float* qkv_b  = (const float*)d_in[6];
    const float* proj_w = (const float*)d_in[7];
    const float* proj_b = (const float*)d_in[8];
    const float* ln2_w  = (const float*)d_in[9];
    const float* ln2_b  = (const float*)d_in[10];
    const float* fc1_w  = (const float*)d_in[11];
    const float* fc1_b  = (const float*)d_in[12];
    const float* fc2_w  = (const float*)d_in[13];
    const float* fc2_b  = (const float*)d_in[14];
    float* out = (float*)d_out;

    float *p_xn, *p_qkv, *p_y, *p_x1, *p_h;
    cudaGetSymbolAddress((void**)&p_xn,  g_xn);
    cudaGetSymbolAddress((void**)&p_qkv, g_qkv);
    cudaGetSymbolAddress((void**)&p_y,   g_y);
    cudaGetSymbolAddress((void**)&p_x1,  g_x1);
    cudaGetSymbolAddress((void**)&p_h,   g_h);

    const int mtiles = (NTOK + 127) / 128;   // 161

    // 1) LN1
    ln_kernel<<<NTOK, 128>>>(x, ln1_w, ln1_b, p_xn);
    // 2) qkv = xn @ qkv_w^T + qkv_b      [20496 x 1536], K=512
    sgemm_tn<0, CDIM><<<dim3(C3 / 128, mtiles), 256>>>(p_xn, qkv_w, qkv_b, nullptr,
                                                       p_qkv, NTOK, C3);
    // 3) sparse attention -> y
    attn_kernel<<<NTOK, 256>>>(p_qkv, which, mask, p_y);
    // 4) x1 = x + y @ proj_w^T + proj_b  K=512
    sgemm_tn<2, CDIM><<<dim3(CDIM / 128, mtiles), 256>>>(p_y, proj_w, proj_b, x,
                                                         p_x1, NTOK, CDIM);
    // 5) LN2
    ln_kernel<<<NTOK, 128>>>(p_x1, ln2_w, ln2_b, p_xn);
    // 6) h = gelu(xn2 @ fc1_w^T + fc1_b)  [20496 x 2048], K=512
    sgemm_tn<1, CDIM><<<dim3(HID / 128, mtiles), 256>>>(p_xn, fc1_w, fc1_b, nullptr,
                                                        p_h, NTOK, HID);
    // 7) out = x1 + h @ fc2_w^T + fc2_b   K=2048
    sgemm_tn<2, HID><<<dim3(CDIM / 128, mtiles), 256>>>(p_h, fc2_w, fc2_b, p_x1,
                                                        out, NTOK, CDIM);
}